// round 1
// baseline (speedup 1.0000x reference)
#include <cuda_runtime.h>

#define Bb 64
#define Nn 64
#define KDIM 512
#define NOUT 480           // NT*SEM = 30*16
#define ROWS (Bb*Nn)       // 4096
#define NSPAN 2016         // N(N-1)/2
#define NP1 65

// Scratch (no allocation allowed) — __device__ globals
__device__ float g_h[ROWS * NOUT];            // 7.86 MB
__device__ float g_prefix[Bb * NP1 * NOUT];   // 7.99 MB
__device__ int   g_ls[NSPAN];
__device__ int   g_rs[NSPAN];

// ---------------------------------------------------------------------------
// Kernel 1: fused gather + GEMM  h = emb[x] @ w_out^T + b_out
// Tiling: BM=128, BN=32, BK=16, 256 threads, 4x4 register tile per thread.
// ---------------------------------------------------------------------------
__global__ __launch_bounds__(256) void gemm_kernel(
    const int* __restrict__ x, const float* __restrict__ emb,
    const float* __restrict__ w, const float* __restrict__ bo)
{
    __shared__ float As[16][128];   // k-major: As[k][m]
    __shared__ float Ws[16][32];    // k-major: Ws[k][n]
    __shared__ int rowidx[128];

    const int tid = threadIdx.x;
    const int m0 = blockIdx.x * 128;
    const int n0 = blockIdx.y * 32;

    if (tid < 128) rowidx[tid] = x[m0 + tid];
    __syncthreads();

    // A loader mapping: 2 threads per row, 8 floats (2x float4) each
    const int arow = tid >> 1;
    const int ahalf = tid & 1;
    const float* abase = emb + (size_t)rowidx[arow] * KDIM + ahalf * 8;

    // W loader mapping: 128 threads, one float4 each (4 threads per n-row)
    const int wnr = tid >> 2;           // 0..63 (only <32 used via tid<128)
    const int wkq = tid & 3;
    const float* wbase = w + (size_t)(n0 + wnr) * KDIM + wkq * 4;

    const int tx = tid & 7;   // 8 col groups of 4
    const int ty = tid >> 3;  // 32 row groups of 4

    float acc[4][4] = {};

    for (int kt = 0; kt < KDIM / 16; kt++) {
        const float4 a0 = *(const float4*)(abase + kt * 16);
        const float4 a1 = *(const float4*)(abase + kt * 16 + 4);
        float4 wv = make_float4(0.f, 0.f, 0.f, 0.f);
        if (tid < 128) wv = *(const float4*)(wbase + kt * 16);

        __syncthreads();  // previous iteration's compute done before overwrite

        As[ahalf * 8 + 0][arow] = a0.x;
        As[ahalf * 8 + 1][arow] = a0.y;
        As[ahalf * 8 + 2][arow] = a0.z;
        As[ahalf * 8 + 3][arow] = a0.w;
        As[ahalf * 8 + 4][arow] = a1.x;
        As[ahalf * 8 + 5][arow] = a1.y;
        As[ahalf * 8 + 6][arow] = a1.z;
        As[ahalf * 8 + 7][arow] = a1.w;
        if (tid < 128) {
            Ws[wkq * 4 + 0][wnr] = wv.x;
            Ws[wkq * 4 + 1][wnr] = wv.y;
            Ws[wkq * 4 + 2][wnr] = wv.z;
            Ws[wkq * 4 + 3][wnr] = wv.w;
        }
        __syncthreads();

#pragma unroll
        for (int k = 0; k < 16; k++) {
            const float4 av = *(const float4*)&As[k][ty * 4];
            const float4 bv = *(const float4*)&Ws[k][tx * 4];
            acc[0][0] = fmaf(av.x, bv.x, acc[0][0]);
            acc[0][1] = fmaf(av.x, bv.y, acc[0][1]);
            acc[0][2] = fmaf(av.x, bv.z, acc[0][2]);
            acc[0][3] = fmaf(av.x, bv.w, acc[0][3]);
            acc[1][0] = fmaf(av.y, bv.x, acc[1][0]);
            acc[1][1] = fmaf(av.y, bv.y, acc[1][1]);
            acc[1][2] = fmaf(av.y, bv.z, acc[1][2]);
            acc[1][3] = fmaf(av.y, bv.w, acc[1][3]);
            acc[2][0] = fmaf(av.z, bv.x, acc[2][0]);
            acc[2][1] = fmaf(av.z, bv.y, acc[2][1]);
            acc[2][2] = fmaf(av.z, bv.z, acc[2][2]);
            acc[2][3] = fmaf(av.z, bv.w, acc[2][3]);
            acc[3][0] = fmaf(av.w, bv.x, acc[3][0]);
            acc[3][1] = fmaf(av.w, bv.y, acc[3][1]);
            acc[3][2] = fmaf(av.w, bv.z, acc[3][2]);
            acc[3][3] = fmaf(av.w, bv.w, acc[3][3]);
        }
    }

    const float4 bv = *(const float4*)(bo + n0 + tx * 4);
#pragma unroll
    for (int i = 0; i < 4; i++) {
        float4 o;
        o.x = acc[i][0] + bv.x;
        o.y = acc[i][1] + bv.y;
        o.z = acc[i][2] + bv.z;
        o.w = acc[i][3] + bv.w;
        *(float4*)(g_h + (size_t)(m0 + ty * 4 + i) * NOUT + n0 + tx * 4) = o;
    }
}

// ---------------------------------------------------------------------------
// Kernel 2: masked cumsum over sequence -> prefix [B, N+1, 480]
// One block per batch, 480 threads (one per output channel).
// ---------------------------------------------------------------------------
__global__ __launch_bounds__(480) void prefix_kernel(const int* __restrict__ lengths)
{
    const int b = blockIdx.x;
    const int o = threadIdx.x;
    const int len = lengths[b];
    float acc = 0.0f;
    g_prefix[((size_t)b * NP1 + 0) * NOUT + o] = 0.0f;
#pragma unroll 8
    for (int n = 0; n < Nn; n++) {
        const float v = g_h[((size_t)b * Nn + n) * NOUT + o];
        if (n < len) acc += v;
        g_prefix[((size_t)b * NP1 + n + 1) * NOUT + o] = acc;
    }
}

// ---------------------------------------------------------------------------
// Kernel 2b: span index table (spans ordered by length k, then left pos l)
// ---------------------------------------------------------------------------
__global__ void spantab_kernel()
{
    const int k = blockIdx.x + 1;   // 1..63
    const int l = threadIdx.x;      // 0..63
    if (l < Nn - k) {
        const int s = (k - 1) * (2 * Nn - k) / 2 + l;
        g_ls[s] = l;
        g_rs[s] = l + k;
    }
}

// ---------------------------------------------------------------------------
// Kernel 3: span features + L2 normalization over SEM=16
// One thread per output element; 16-lane shfl butterfly for the norm.
// ---------------------------------------------------------------------------
__global__ __launch_bounds__(256) void span_kernel(float* __restrict__ out)
{
    const int gid = blockIdx.x * 256 + threadIdx.x;
    const int o = gid % NOUT;            // nt*16 + sem (group of 16 = one (b,s,nt))
    const int rest = gid / NOUT;
    const int s = rest % NSPAN;
    const int b = rest / NSPAN;

    const int l = g_ls[s];
    const int r = g_rs[s];

    const float* pb = g_prefix + (size_t)b * NP1 * NOUT;
    const float d = pb[(size_t)(r + 1) * NOUT + o] - pb[(size_t)l * NOUT + o];

    float sq = d * d;
    sq += __shfl_xor_sync(0xffffffffu, sq, 8);
    sq += __shfl_xor_sync(0xffffffffu, sq, 4);
    sq += __shfl_xor_sync(0xffffffffu, sq, 2);
    sq += __shfl_xor_sync(0xffffffffu, sq, 1);

    out[gid] = d * rsqrtf(sq);
}

// ---------------------------------------------------------------------------
extern "C" void kernel_launch(void* const* d_in, const int* in_sizes, int n_in,
                              void* d_out, int out_size)
{
    const int*   x       = (const int*)d_in[0];
    const int*   lengths = (const int*)d_in[1];
    const float* emb     = (const float*)d_in[2];
    const float* w_out   = (const float*)d_in[3];
    const float* b_out   = (const float*)d_in[4];
    float* out = (float*)d_out;

    gemm_kernel<<<dim3(ROWS / 128, NOUT / 32), 256>>>(x, emb, w_out, b_out);
    spantab_kernel<<<Nn - 1, Nn>>>();
    prefix_kernel<<<Bb, NOUT>>>(lengths);

    const long long total = (long long)Bb * NSPAN * NOUT;  // 61,931,520
    span_kernel<<<(unsigned)(total / 256), 256>>>(out);
}

// round 2
// speedup vs baseline: 1.2554x; 1.2554x over previous
#include <cuda_runtime.h>

#define Bb 64
#define Nn 64
#define KDIM 512
#define NOUT 480           // NT*SEM = 30*16
#define NT 30
#define ROWS (Bb*Nn)       // 4096
#define NSPAN 2016         // N(N-1)/2
#define NP1 65

// Scratch (no allocation allowed) — __device__ globals
__device__ float g_h[ROWS * NOUT];            // 7.86 MB
__device__ float g_prefix[Bb * NP1 * NOUT];   // 7.99 MB
__device__ int   g_lr[NSPAN];                 // packed l | (r<<8)

// ---------------------------------------------------------------------------
// Kernel 1: fused gather + GEMM  h = emb[x] @ w_out^T + b_out
// Tiling: BM=128, BN=32, BK=16, 256 threads, 4x4 register tile per thread.
// ---------------------------------------------------------------------------
__global__ __launch_bounds__(256) void gemm_kernel(
    const int* __restrict__ x, const float* __restrict__ emb,
    const float* __restrict__ w, const float* __restrict__ bo)
{
    __shared__ float As[16][128];   // k-major: As[k][m]
    __shared__ float Ws[16][32];    // k-major: Ws[k][n]
    __shared__ int rowidx[128];

    const int tid = threadIdx.x;
    const int m0 = blockIdx.x * 128;
    const int n0 = blockIdx.y * 32;

    if (tid < 128) rowidx[tid] = x[m0 + tid];
    __syncthreads();

    // A loader mapping: 2 threads per row, 8 floats (2x float4) each
    const int arow = tid >> 1;
    const int ahalf = tid & 1;
    const float* abase = emb + (size_t)rowidx[arow] * KDIM + ahalf * 8;

    // W loader mapping: 128 threads, one float4 each (4 threads per n-row)
    const int wnr = tid >> 2;
    const int wkq = tid & 3;
    const float* wbase = w + (size_t)(n0 + wnr) * KDIM + wkq * 4;

    const int tx = tid & 7;   // 8 col groups of 4
    const int ty = tid >> 3;  // 32 row groups of 4

    float acc[4][4] = {};

    for (int kt = 0; kt < KDIM / 16; kt++) {
        const float4 a0 = *(const float4*)(abase + kt * 16);
        const float4 a1 = *(const float4*)(abase + kt * 16 + 4);
        float4 wv = make_float4(0.f, 0.f, 0.f, 0.f);
        if (tid < 128) wv = *(const float4*)(wbase + kt * 16);

        __syncthreads();  // previous iteration's compute done before overwrite

        As[ahalf * 8 + 0][arow] = a0.x;
        As[ahalf * 8 + 1][arow] = a0.y;
        As[ahalf * 8 + 2][arow] = a0.z;
        As[ahalf * 8 + 3][arow] = a0.w;
        As[ahalf * 8 + 4][arow] = a1.x;
        As[ahalf * 8 + 5][arow] = a1.y;
        As[ahalf * 8 + 6][arow] = a1.z;
        As[ahalf * 8 + 7][arow] = a1.w;
        if (tid < 128) {
            Ws[wkq * 4 + 0][wnr] = wv.x;
            Ws[wkq * 4 + 1][wnr] = wv.y;
            Ws[wkq * 4 + 2][wnr] = wv.z;
            Ws[wkq * 4 + 3][wnr] = wv.w;
        }
        __syncthreads();

#pragma unroll
        for (int k = 0; k < 16; k++) {
            const float4 av = *(const float4*)&As[k][ty * 4];
            const float4 bv = *(const float4*)&Ws[k][tx * 4];
            acc[0][0] = fmaf(av.x, bv.x, acc[0][0]);
            acc[0][1] = fmaf(av.x, bv.y, acc[0][1]);
            acc[0][2] = fmaf(av.x, bv.z, acc[0][2]);
            acc[0][3] = fmaf(av.x, bv.w, acc[0][3]);
            acc[1][0] = fmaf(av.y, bv.x, acc[1][0]);
            acc[1][1] = fmaf(av.y, bv.y, acc[1][1]);
            acc[1][2] = fmaf(av.y, bv.z, acc[1][2]);
            acc[1][3] = fmaf(av.y, bv.w, acc[1][3]);
            acc[2][0] = fmaf(av.z, bv.x, acc[2][0]);
            acc[2][1] = fmaf(av.z, bv.y, acc[2][1]);
            acc[2][2] = fmaf(av.z, bv.z, acc[2][2]);
            acc[2][3] = fmaf(av.z, bv.w, acc[2][3]);
            acc[3][0] = fmaf(av.w, bv.x, acc[3][0]);
            acc[3][1] = fmaf(av.w, bv.y, acc[3][1]);
            acc[3][2] = fmaf(av.w, bv.z, acc[3][2]);
            acc[3][3] = fmaf(av.w, bv.w, acc[3][3]);
        }
    }

    const float4 bv = *(const float4*)(bo + n0 + tx * 4);
#pragma unroll
    for (int i = 0; i < 4; i++) {
        float4 o;
        o.x = acc[i][0] + bv.x;
        o.y = acc[i][1] + bv.y;
        o.z = acc[i][2] + bv.z;
        o.w = acc[i][3] + bv.w;
        *(float4*)(g_h + (size_t)(m0 + ty * 4 + i) * NOUT + n0 + tx * 4) = o;
    }
}

// ---------------------------------------------------------------------------
// Kernel 2: masked cumsum over sequence -> prefix [B, N+1, 480]
// ---------------------------------------------------------------------------
__global__ __launch_bounds__(480) void prefix_kernel(const int* __restrict__ lengths)
{
    const int b = blockIdx.x;
    const int o = threadIdx.x;
    const int len = lengths[b];
    float acc = 0.0f;
    g_prefix[((size_t)b * NP1 + 0) * NOUT + o] = 0.0f;
#pragma unroll 8
    for (int n = 0; n < Nn; n++) {
        const float v = g_h[((size_t)b * Nn + n) * NOUT + o];
        if (n < len) acc += v;
        g_prefix[((size_t)b * NP1 + n + 1) * NOUT + o] = acc;
    }
}

// ---------------------------------------------------------------------------
// Kernel 2b: packed span index table (spans ordered by length k, then l)
// ---------------------------------------------------------------------------
__global__ void spantab_kernel()
{
    const int k = blockIdx.x + 1;   // 1..63
    const int l = threadIdx.x;      // 0..63
    if (l < Nn - k) {
        const int s = (k - 1) * (2 * Nn - k) / 2 + l;
        g_lr[s] = l | ((l + k) << 8);
    }
}

// ---------------------------------------------------------------------------
// Kernel 3: span features + L2 normalization over SEM=16
// ONE THREAD per (b, s, nt) group: vector loads, in-register norm, no shfl.
// ---------------------------------------------------------------------------
__global__ __launch_bounds__(256) void span_kernel(float* __restrict__ out)
{
    const int gid = blockIdx.x * 256 + threadIdx.x;   // (b*NSPAN + s)*NT + nt
    const int nt = gid % NT;
    const int rest = gid / NT;
    const int s = rest % NSPAN;
    const int b = rest / NSPAN;

    const int lr = g_lr[s];
    const int l = lr & 0xff;
    const int r = lr >> 8;

    const float* pb = g_prefix + (size_t)b * NP1 * NOUT + nt * 16;
    const float4* p1 = (const float4*)(pb + (size_t)(r + 1) * NOUT);
    const float4* p0 = (const float4*)(pb + (size_t)l * NOUT);

    float4 d[4];
    float sq = 0.0f;
#pragma unroll
    for (int j = 0; j < 4; j++) {
        const float4 a = p1[j];
        const float4 c = p0[j];
        d[j].x = a.x - c.x;
        d[j].y = a.y - c.y;
        d[j].z = a.z - c.z;
        d[j].w = a.w - c.w;
        sq = fmaf(d[j].x, d[j].x, sq);
        sq = fmaf(d[j].y, d[j].y, sq);
        sq = fmaf(d[j].z, d[j].z, sq);
        sq = fmaf(d[j].w, d[j].w, sq);
    }

    const float inv = rsqrtf(sq);

    float4* o = (float4*)(out + (size_t)gid * 16);
#pragma unroll
    for (int j = 0; j < 4; j++) {
        d[j].x *= inv;
        d[j].y *= inv;
        d[j].z *= inv;
        d[j].w *= inv;
        o[j] = d[j];
    }
}

// ---------------------------------------------------------------------------
extern "C" void kernel_launch(void* const* d_in, const int* in_sizes, int n_in,
                              void* d_out, int out_size)
{
    const int*   x       = (const int*)d_in[0];
    const int*   lengths = (const int*)d_in[1];
    const float* emb     = (const float*)d_in[2];
    const float* w_out   = (const float*)d_in[3];
    const float* b_out   = (const float*)d_in[4];
    float* out = (float*)d_out;

    gemm_kernel<<<dim3(ROWS / 128, NOUT / 32), 256>>>(x, emb, w_out, b_out);
    spantab_kernel<<<Nn - 1, Nn>>>();
    prefix_kernel<<<Bb, NOUT>>>(lengths);

    const int groups = Bb * NSPAN * NT;        // 3,870,720
    span_kernel<<<groups / 256, 256>>>(out);   // 15,120 blocks
}

// round 3
// speedup vs baseline: 1.8320x; 1.4592x over previous
#include <cuda_runtime.h>
#include <cstdint>

#define Bb 64
#define Nn 64
#define KDIM 512
#define NOUT 480           // NT*SEM = 30*16
#define NT 30
#define ROWS 4096
#define NSPAN 2016
#define NP1 65

// Scratch — __device__ globals (no allocation allowed)
__device__ float g_h[ROWS * NOUT];            // 7.86 MB
__device__ float g_prefix[Bb * NP1 * NOUT];   // 7.99 MB

// ---------------------------------------------------------------------------
// Kernel 1: fused gather + GEMM  h = emb[x] @ w_out^T + b_out
// BM=64, BN=96, BK=16, 96 threads. Thread tile 16(m)x4(n) as 8 m-pairs,
// packed f32x2 FFMA2 accumulation (2 FLOPs per fma-pipe issue).
// ---------------------------------------------------------------------------
#define BM 64
#define BN 96
#define BK 16
#define GTH 96
#define ASTRIDE 68   // padded: STS bank conflicts 4-way -> 2-way

__global__ __launch_bounds__(GTH) void gemm_kernel(
    const int* __restrict__ x, const float* __restrict__ emb,
    const float* __restrict__ w, const float* __restrict__ bo)
{
    __shared__ float As[BK][ASTRIDE];   // k-major: As[k][m], m<64
    __shared__ float Ws[BK][BN];        // k-major: Ws[k][n]
    __shared__ int rowidx[BM];

    const int tid = threadIdx.x;
    const int m0 = blockIdx.x * BM;
    const int n0 = blockIdx.y * BN;

    if (tid < BM) rowidx[tid] = x[m0 + tid];
    __syncthreads();

    const int tx = tid % 24;   // n: cols tx*4
    const int ty = tid / 24;   // m: rows ty*16 (8 pairs)

    unsigned long long acc[8][4];
#pragma unroll
    for (int p = 0; p < 8; p++)
#pragma unroll
        for (int j = 0; j < 4; j++) acc[p][j] = 0ull;

    for (int kt = 0; kt < KDIM / BK; kt++) {
        // ---- fetch A (64 rows x 16 k) : 256 float4, idx -> m=idx>>2, kq=idx&3
        float4 av[3];
#pragma unroll
        for (int it = 0; it < 3; it++) {
            const int idx = tid + it * GTH;
            if (idx < 256) {
                const int m = idx >> 2, kq = idx & 3;
                av[it] = *(const float4*)(emb + (size_t)rowidx[m] * KDIM + kt * BK + kq * 4);
            }
        }
        // ---- fetch W: thread tid owns row n0+tid, 4 contiguous float4
        float4 wv[4];
#pragma unroll
        for (int it = 0; it < 4; it++)
            wv[it] = *(const float4*)(w + (size_t)(n0 + tid) * KDIM + kt * BK + it * 4);

        __syncthreads();   // previous compute done before smem overwrite

#pragma unroll
        for (int it = 0; it < 3; it++) {
            const int idx = tid + it * GTH;
            if (idx < 256) {
                const int m = idx >> 2, kq = idx & 3;
                As[kq * 4 + 0][m] = av[it].x;
                As[kq * 4 + 1][m] = av[it].y;
                As[kq * 4 + 2][m] = av[it].z;
                As[kq * 4 + 3][m] = av[it].w;
            }
        }
#pragma unroll
        for (int it = 0; it < 4; it++) {
            Ws[it * 4 + 0][tid] = wv[it].x;
            Ws[it * 4 + 1][tid] = wv[it].y;
            Ws[it * 4 + 2][tid] = wv[it].z;
            Ws[it * 4 + 3][tid] = wv[it].w;
        }
        __syncthreads();

#pragma unroll
        for (int k = 0; k < BK; k++) {
            // a: 8 m-pairs, naturally packed (m, m+1) from k-major smem
            const ulonglong2* ap = (const ulonglong2*)&As[k][ty * 16];
            unsigned long long a[8];
#pragma unroll
            for (int q = 0; q < 4; q++) {
                const ulonglong2 v = ap[q];
                a[q * 2 + 0] = v.x;
                a[q * 2 + 1] = v.y;
            }
            // b: 4 scalars, duplicated into both f32x2 lanes
            const uint4 bu = *(const uint4*)&Ws[k][tx * 4];
            unsigned long long bd[4];
            asm("mov.b64 %0, {%1, %1};" : "=l"(bd[0]) : "r"(bu.x));
            asm("mov.b64 %0, {%1, %1};" : "=l"(bd[1]) : "r"(bu.y));
            asm("mov.b64 %0, {%1, %1};" : "=l"(bd[2]) : "r"(bu.z));
            asm("mov.b64 %0, {%1, %1};" : "=l"(bd[3]) : "r"(bu.w));
#pragma unroll
            for (int p = 0; p < 8; p++)
#pragma unroll
                for (int j = 0; j < 4; j++)
                    asm("fma.rn.f32x2 %0, %1, %2, %0;"
                        : "+l"(acc[p][j]) : "l"(a[p]), "l"(bd[j]));
        }
    }

    // epilogue: unpack pairs, add bias, store
    const float4 bb = *(const float4*)(bo + n0 + tx * 4);
#pragma unroll
    for (int p = 0; p < 8; p++) {
        unsigned lo[4], hi[4];
#pragma unroll
        for (int j = 0; j < 4; j++)
            asm("mov.b64 {%0, %1}, %2;" : "=r"(lo[j]), "=r"(hi[j]) : "l"(acc[p][j]));
        const int row0 = m0 + ty * 16 + 2 * p;
        float4 o0, o1;
        o0.x = __uint_as_float(lo[0]) + bb.x;
        o0.y = __uint_as_float(lo[1]) + bb.y;
        o0.z = __uint_as_float(lo[2]) + bb.z;
        o0.w = __uint_as_float(lo[3]) + bb.w;
        o1.x = __uint_as_float(hi[0]) + bb.x;
        o1.y = __uint_as_float(hi[1]) + bb.y;
        o1.z = __uint_as_float(hi[2]) + bb.z;
        o1.w = __uint_as_float(hi[3]) + bb.w;
        *(float4*)(g_h + (size_t)row0 * NOUT + n0 + tx * 4) = o0;
        *(float4*)(g_h + (size_t)(row0 + 1) * NOUT + n0 + tx * 4) = o1;
    }
}

// ---------------------------------------------------------------------------
// Kernel 2: masked cumsum over sequence -> prefix [B, N+1, 480]
// ---------------------------------------------------------------------------
__global__ __launch_bounds__(480) void prefix_kernel(const int* __restrict__ lengths)
{
    const int b = blockIdx.x;
    const int o = threadIdx.x;
    const int len = lengths[b];
    float acc = 0.0f;
    g_prefix[((size_t)b * NP1 + 0) * NOUT + o] = 0.0f;
#pragma unroll 8
    for (int n = 0; n < Nn; n++) {
        const float v = g_h[((size_t)b * Nn + n) * NOUT + o];
        if (n < len) acc += v;
        g_prefix[((size_t)b * NP1 + n + 1) * NOUT + o] = acc;
    }
}

// ---------------------------------------------------------------------------
// Kernel 3: span features + L2 norm, smem-tiled over 8x8 (l, r) tiles.
// Block = (tile, b): loads 8 L-rows + 8 R-rows (30KB) once, computes 64 spans.
// Thread owns 8 floats of a span as two dense float4 halves; 4-lane butterfly
// reduces two 16-float groups at once.
// ---------------------------------------------------------------------------
#define STH 256

__global__ __launch_bounds__(STH) void span_kernel(float* __restrict__ out)
{
    __shared__ float sL[8][NOUT];
    __shared__ float sR[8][NOUT];

    const int b = blockIdx.y;
    const int t = blockIdx.x;                 // 0..35, t = rt*(rt+1)/2 + lt
    int rt = 0;
    while ((rt + 1) * (rt + 2) / 2 <= t) rt++;
    const int lt = t - rt * (rt + 1) / 2;

    const int tid = threadIdx.x;
    const float* pb = g_prefix + (size_t)b * NP1 * NOUT;

    // load 16 rows x 480 floats = 1920 float4, fully dense
    for (int i4 = tid; i4 < 16 * (NOUT / 4); i4 += STH) {
        const int row = i4 / (NOUT / 4);
        const int pos = i4 % (NOUT / 4);
        const int grow = (row < 8) ? (lt * 8 + row) : (rt * 8 + (row - 8) + 1);
        const float4 v = *(const float4*)(pb + (size_t)grow * NOUT + pos * 4);
        if (row < 8) *(float4*)&sL[row][pos * 4] = v;
        else         *(float4*)&sR[row - 8][pos * 4] = v;
    }
    __syncthreads();

    const int slot = tid / 60;        // 0..3 active, 4 = spare (tid 240..255)
    const int lane = tid % 60;
    const int base = (slot < 4) ? slot : 0;
    const bool diag = (lt == rt);

#pragma unroll 4
    for (int i = 0; i < 16; i++) {
        const int sp = base + 4 * i;          // 0..63
        const int li = sp & 7;
        const int ri = sp >> 3;

        const float4* Rp = (const float4*)&sR[ri][0];
        const float4* Lp = (const float4*)&sL[li][0];
        const float4 ra = Rp[lane],      la = Lp[lane];        // floats lane*4
        const float4 rb = Rp[60 + lane], lb = Lp[60 + lane];   // floats 240+lane*4

        float4 da, db;
        da.x = ra.x - la.x; da.y = ra.y - la.y; da.z = ra.z - la.z; da.w = ra.w - la.w;
        db.x = rb.x - lb.x; db.y = rb.y - lb.y; db.z = rb.z - lb.z; db.w = rb.w - lb.w;

        float sqA = da.x * da.x;
        sqA = fmaf(da.y, da.y, sqA); sqA = fmaf(da.z, da.z, sqA); sqA = fmaf(da.w, da.w, sqA);
        float sqB = db.x * db.x;
        sqB = fmaf(db.y, db.y, sqB); sqB = fmaf(db.z, db.z, sqB); sqB = fmaf(db.w, db.w, sqB);

        // two independent 4-lane butterflies (quads are warp-aligned)
        sqA += __shfl_xor_sync(0xffffffffu, sqA, 1);
        sqA += __shfl_xor_sync(0xffffffffu, sqA, 2);
        sqB += __shfl_xor_sync(0xffffffffu, sqB, 1);
        sqB += __shfl_xor_sync(0xffffffffu, sqB, 2);

        const float invA = rsqrtf(sqA);
        const float invB = rsqrtf(sqB);

        if (slot < 4 && (!diag || li < ri)) {
            const int l = lt * 8 + li;
            const int r = rt * 8 + ri;
            const int k = r - l;
            const int s = (((k - 1) * (128 - k)) >> 1) + l;
            float* op = out + (size_t)(b * NSPAN + s) * NOUT;
            float4 oa, ob;
            oa.x = da.x * invA; oa.y = da.y * invA; oa.z = da.z * invA; oa.w = da.w * invA;
            ob.x = db.x * invB; ob.y = db.y * invB; ob.z = db.z * invB; ob.w = db.w * invB;
            *(float4*)(op + lane * 4) = oa;
            *(float4*)(op + 240 + lane * 4) = ob;
        }
    }
}

// ---------------------------------------------------------------------------
extern "C" void kernel_launch(void* const* d_in, const int* in_sizes, int n_in,
                              void* d_out, int out_size)
{
    const int*   x       = (const int*)d_in[0];
    const int*   lengths = (const int*)d_in[1];
    const float* emb     = (const float*)d_in[2];
    const float* w_out   = (const float*)d_in[3];
    const float* b_out   = (const float*)d_in[4];
    float* out = (float*)d_out;

    gemm_kernel<<<dim3(ROWS / BM, NOUT / BN), GTH>>>(x, emb, w_out, b_out);
    prefix_kernel<<<Bb, NOUT>>>(lengths);
    span_kernel<<<dim3(36, Bb), STH>>>(out);
}